// round 6
// baseline (speedup 1.0000x reference)
#include <cuda_runtime.h>
#include <cstdint>
#include <math.h>

#define NE 8
#define NTOK 16384
#define DIM 1024
#define FF 2048
#define NKT1 (DIM / 32)
#define NKT2 (FF / 32)

// ---------------- scratch (device globals; no allocation) ----------------
__device__ int   g_counts[NE];
__device__ int   g_offsets[NE + 1];
__device__ int   g_tok[NE * NTOK];
__device__ float g_cw[NE * NTOK];
__device__ float g_H[(size_t)2 * NTOK * FF];            // 256 MiB hidden acts (tf32-rounded)
__device__ float g_xr[(size_t)NTOK * DIM];              // tf32-rounded x
__device__ float g_w1r[(size_t)NE * FF * DIM];          // tf32-rounded w1
__device__ float g_w2r[(size_t)NE * DIM * FF];          // tf32-rounded w2
__device__ float g_w3r[(size_t)NE * FF * DIM];          // tf32-rounded w3

// ---------------- helpers ----------------
__device__ __forceinline__ unsigned f2tf(float f) {
    unsigned u;
    asm("cvt.rna.tf32.f32 %0, %1;" : "=r"(u) : "f"(f));
    return u;
}
__device__ __forceinline__ float f2tf_f(float f) { return __uint_as_float(f2tf(f)); }
__device__ __forceinline__ float4 cvt4(float4 v) {
    float4 r;
    r.x = f2tf_f(v.x); r.y = f2tf_f(v.y); r.z = f2tf_f(v.z); r.w = f2tf_f(v.w);
    return r;
}

static __device__ __forceinline__ uint32_t smem_u32(const void* p) {
    uint32_t a;
    asm("{ .reg .u64 t; cvta.to.shared.u64 t, %1; cvt.u32.u64 %0, t; }" : "=r"(a) : "l"(p));
    return a;
}

__device__ __forceinline__ void mma8u(float* c, const uint32_t* a, const uint32_t* b) {
    asm volatile(
        "mma.sync.aligned.m16n8k8.row.col.f32.tf32.tf32.f32 "
        "{%0,%1,%2,%3},{%4,%5,%6,%7},{%8,%9},{%0,%1,%2,%3};"
        : "+f"(c[0]), "+f"(c[1]), "+f"(c[2]), "+f"(c[3])
        : "r"(a[0]), "r"(a[1]), "r"(a[2]), "r"(a[3]), "r"(b[0]), "r"(b[1]));
}

#define LDSM4(r0_, r1_, r2_, r3_, addr)                                        \
    asm volatile("ldmatrix.sync.aligned.m8n8.x4.shared.b16 {%0,%1,%2,%3}, [%4];" \
        : "=r"(r0_), "=r"(r1_), "=r"(r2_), "=r"(r3_) : "r"(addr))

__device__ __forceinline__ void cpa16(uint32_t dst, const void* src, uint32_t nbytes) {
    asm volatile("cp.async.cg.shared.global [%0], [%1], 16, %2;"
                 :: "r"(dst), "l"(src), "r"(nbytes) : "memory");
}
#define CP_COMMIT() asm volatile("cp.async.commit_group;" ::: "memory")
#define CP_WAIT1()  asm volatile("cp.async.wait_group 1;" ::: "memory")

// 128B-row swizzle: row r, 16B-chunk c (0..7) -> phys chunk c ^ (r&7).
// ldmatrix reads 8 consecutive rows at fixed logical c -> 8 distinct chunks: conflict-free.
__device__ __forceinline__ uint32_t swb32(int r, int c) {
    return (uint32_t)(r * 128 + ((c ^ r) & 7) * 16);
}

// ---------------- kernel: round fp32 -> tf32 (grid-stride float4) ----------------
__global__ void round_kernel(const float* __restrict__ src, float* __restrict__ dst, int n4) {
    int i = blockIdx.x * blockDim.x + threadIdx.x;
    if (i < n4)
        ((float4*)dst)[i] = cvt4(((const float4*)src)[i]);
}

// ---------------- kernel 0: zero output + counts ----------------
__global__ void zero_kernel(float* out, int n) {
    int i = blockIdx.x * blockDim.x + threadIdx.x;
    if (i < n) out[i] = 0.0f;
    if (blockIdx.x == 0 && threadIdx.x < NE) g_counts[threadIdx.x] = 0;
}

// ---------------- kernel 1: gating + routing (one warp per token) ----------------
__global__ void gate_kernel(const float* __restrict__ x, const float* __restrict__ gw) {
    int warp = threadIdx.x >> 5;
    int lane = threadIdx.x & 31;
    int token = blockIdx.x * 8 + warp;

    const float* xr = x + (size_t)token * DIM;
    float xv[32];
#pragma unroll
    for (int j = 0; j < 32; j++) xv[j] = xr[j * 32 + lane];

    float logits[NE];
#pragma unroll
    for (int e = 0; e < NE; e++) {
        const float* g = gw + e * DIM;
        float s = 0.0f;
#pragma unroll
        for (int j = 0; j < 32; j++) s += xv[j] * g[j * 32 + lane];
#pragma unroll
        for (int o = 16; o; o >>= 1) s += __shfl_xor_sync(0xffffffffu, s, o);
        logits[e] = s;
    }

    if (lane == 0) {
        int i1 = 0;
#pragma unroll
        for (int e = 1; e < NE; e++)
            if (logits[e] > logits[i1]) i1 = e;
        int i2 = -1;
#pragma unroll
        for (int e = 0; e < NE; e++) {
            if (e == i1) continue;
            if (i2 < 0 || logits[e] > logits[i2]) i2 = e;
        }
        float p1 = 1.0f / (1.0f + __expf(logits[i2] - logits[i1]));
        float p2 = 1.0f - p1;
        int s1 = atomicAdd(&g_counts[i1], 1);
        g_tok[i1 * NTOK + s1] = token;
        g_cw[i1 * NTOK + s1]  = p1;
        int s2 = atomicAdd(&g_counts[i2], 1);
        g_tok[i2 * NTOK + s2] = token;
        g_cw[i2 * NTOK + s2]  = p2;
    }
}

// ---------------- kernel 2: prefix over 8 counts ----------------
__global__ void prefix_kernel() {
    if (threadIdx.x == 0) {
        int a = 0;
        for (int e = 0; e < NE; e++) { g_offsets[e] = a; a += g_counts[e]; }
        g_offsets[NE] = a;
    }
}

// ---------------- tile scheduler ----------------
__device__ __forceinline__ bool find_tile(int bx, int& e, int& tile, int& cnt) {
    int acc = 0;
    e = -1;
#pragma unroll
    for (int ee = 0; ee < NE; ee++) {
        int c = g_counts[ee];
        int t = (c + 127) >> 7;
        if (e < 0 && bx < acc + t) { e = ee; tile = bx - acc; cnt = c; }
        acc += t;
    }
    return e >= 0;
}

// SMEM (dynamic): [0:512) stok, [512:1024) scw, stages at 1024 + s*32768
#define STG_BASE 1024
#define STG_SZ   32768
#define SMEM_BYTES (STG_BASE + 3 * STG_SZ)

// ---------------- kernel 3: GEMM1 (xr@w1r^T, xr@w3r^T) -> silu*mul -> H(tf32) ----------------
// BM=128, BN=64 (dual B), BK=32; 3-stage cp.async pipeline, LDSM operand path
__global__ __launch_bounds__(256, 2) void gemm1_kernel() {
    extern __shared__ char dsm[];
    int e, tile, cnt;
    if (!find_tile(blockIdx.x, e, tile, cnt)) return;
    int offs = g_offsets[e];
    int n0 = blockIdx.y * 64;

    int tid = threadIdx.x;
    int* stok = (int*)dsm;
    if (tid < 128) {
        int i = tile * 128 + tid;
        stok[tid] = (i < cnt) ? g_tok[e * NTOK + i] : -1;
    }
    __syncthreads();

    int warp = tid >> 5, lane = tid & 31;
    int wm = warp >> 1, wn = warp & 1;
    uint32_t sb = smem_u32(dsm);

    // ---- cp.async assignments ----
    // A: 128 rows x 8 chunks = 1024, 4/thread; B1/B3: 64x8 = 512, 2/thread each
    const float* asrc[4]; uint32_t asz[4], adst[4];
#pragma unroll
    for (int j = 0; j < 4; j++) {
        int idx = tid + j * 256;
        int r = idx >> 3, c = idx & 7;
        int t = stok[r];
        asrc[j] = g_xr + (size_t)(t < 0 ? 0 : t) * DIM + c * 4;
        asz[j]  = (t < 0) ? 0u : 16u;
        adst[j] = swb32(r, c);
    }
    const float* b1src[2]; const float* b3src[2]; uint32_t bdst[2];
#pragma unroll
    for (int j = 0; j < 2; j++) {
        int idx = tid + j * 256;
        int r = idx >> 3, c = idx & 7;
        b1src[j] = g_w1r + (size_t)e * FF * DIM + (size_t)(n0 + r) * DIM + c * 4;
        b3src[j] = g_w3r + (size_t)e * FF * DIM + (size_t)(n0 + r) * DIM + c * 4;
        bdst[j]  = swb32(r, c);
    }
    auto issue_stage = [&](int s, int kt) {
        uint32_t base = sb + STG_BASE + s * STG_SZ;
        int k0 = kt * 32;
#pragma unroll
        for (int j = 0; j < 4; j++) cpa16(base + adst[j], asrc[j] + k0, asz[j]);
#pragma unroll
        for (int j = 0; j < 2; j++) cpa16(base + 16384 + bdst[j], b1src[j] + k0, 16);
#pragma unroll
        for (int j = 0; j < 2; j++) cpa16(base + 24576 + bdst[j], b3src[j] + k0, 16);
    };

    // ---- ldmatrix fragment offsets ----
    int arow = (((lane >> 3) & 1) << 3) + (lane & 7);
    int acol = lane >> 4;
    int brow = (((lane >> 4) & 1) << 3) + (lane & 7);
    int bcol = (lane >> 3) & 1;
    uint32_t offA[2][4], offB[2][4];
#pragma unroll
    for (int mt = 0; mt < 2; mt++)
#pragma unroll
        for (int kki = 0; kki < 4; kki++)
            offA[mt][kki] = swb32(wm * 32 + mt * 16 + arow, kki * 2 + acol);
#pragma unroll
    for (int p = 0; p < 2; p++)
#pragma unroll
        for (int kki = 0; kki < 4; kki++)
            offB[p][kki] = swb32(wn * 32 + p * 16 + brow, kki * 2 + bcol);

    float acc1[2][4][4] = {};
    float acc3[2][4][4] = {};

    auto compute_stage = [&](int s) {
        uint32_t base = sb + STG_BASE + s * STG_SZ;
        uint32_t aA = base, aB1 = base + 16384, aB3 = base + 24576;
#pragma unroll
        for (int kki = 0; kki < 4; kki++) {
            uint32_t a[2][4];
            LDSM4(a[0][0], a[0][1], a[0][2], a[0][3], aA + offA[0][kki]);
            LDSM4(a[1][0], a[1][1], a[1][2], a[1][3], aA + offA[1][kki]);
#pragma unroll
            for (int p = 0; p < 2; p++) {
                uint32_t b1[4], b3[4];
                LDSM4(b1[0], b1[1], b1[2], b1[3], aB1 + offB[p][kki]);
                LDSM4(b3[0], b3[1], b3[2], b3[3], aB3 + offB[p][kki]);
#pragma unroll
                for (int mt = 0; mt < 2; mt++) {
                    mma8u(acc1[mt][2 * p],     a[mt], &b1[0]);
                    mma8u(acc1[mt][2 * p + 1], a[mt], &b1[2]);
                    mma8u(acc3[mt][2 * p],     a[mt], &b3[0]);
                    mma8u(acc3[mt][2 * p + 1], a[mt], &b3[2]);
                }
            }
        }
    };

    issue_stage(0, 0); CP_COMMIT();
    issue_stage(1, 1); CP_COMMIT();
#pragma unroll 1
    for (int kt = 0; kt < NKT1; kt++) {
        CP_WAIT1();
        __syncthreads();
        compute_stage(kt % 3);
        if (kt + 2 < NKT1) issue_stage((kt + 2) % 3, kt + 2);
        CP_COMMIT();
    }

    // epilogue: h = tf32(silu(s1) * s3) -> g_H
#pragma unroll
    for (int mt = 0; mt < 2; mt++) {
#pragma unroll
        for (int nt = 0; nt < 4; nt++) {
#pragma unroll
            for (int q = 0; q < 4; q++) {
                int r  = wm * 32 + mt * 16 + (lane >> 2) + ((q >= 2) ? 8 : 0);
                int cc = wn * 32 + nt * 8 + ((lane & 3) << 1) + (q & 1);
                int i = tile * 128 + r;
                if (i < cnt) {
                    float s1 = acc1[mt][nt][q], s3 = acc3[mt][nt][q];
                    float h = (s1 / (1.0f + __expf(-s1))) * s3;
                    g_H[(size_t)(offs + i) * FF + n0 + cc] = f2tf_f(h);
                }
            }
        }
    }
}

// ---------------- kernel 4: GEMM2 (H @ w2r^T), BN=128, scaled scatter-add ----------------
__global__ __launch_bounds__(256, 2) void gemm2_kernel(float* __restrict__ out) {
    extern __shared__ char dsm[];
    int e, tile, cnt;
    if (!find_tile(blockIdx.x, e, tile, cnt)) return;
    int offs = g_offsets[e];
    int n0 = blockIdx.y * 128;

    int tid = threadIdx.x;
    int*   stok = (int*)dsm;
    float* scw  = (float*)(dsm + 512);
    if (tid < 128) {
        int i = tile * 128 + tid;
        stok[tid] = (i < cnt) ? g_tok[e * NTOK + i] : -1;
        scw[tid]  = (i < cnt) ? g_cw[e * NTOK + i] : 0.0f;
    }
    __syncthreads();

    int warp = tid >> 5, lane = tid & 31;
    int wm = warp >> 1, wn = warp & 1;
    uint32_t sb = smem_u32(dsm);

    // A: 128x8 chunks, 4/thread from g_H; B: 128x8 chunks, 4/thread from w2r
    const float* asrc[4]; uint32_t asz[4], adst[4];
    const float* bsrc[4];
#pragma unroll
    for (int j = 0; j < 4; j++) {
        int idx = tid + j * 256;
        int r = idx >> 3, c = idx & 7;
        bool av = (tile * 128 + r) < cnt;
        asrc[j] = g_H + (size_t)(offs + tile * 128 + (av ? r : 0)) * FF + c * 4;
        asz[j]  = av ? 16u : 0u;
        adst[j] = swb32(r, c);
        bsrc[j] = g_w2r + (size_t)e * DIM * FF + (size_t)(n0 + r) * FF + c * 4;
    }
    auto issue_stage = [&](int s, int kt) {
        uint32_t base = sb + STG_BASE + s * STG_SZ;
        int k0 = kt * 32;
#pragma unroll
        for (int j = 0; j < 4; j++) cpa16(base + adst[j], asrc[j] + k0, asz[j]);
#pragma unroll
        for (int j = 0; j < 4; j++) cpa16(base + 16384 + adst[j], bsrc[j] + k0, 16);
    };

    int arow = (((lane >> 3) & 1) << 3) + (lane & 7);
    int acol = lane >> 4;
    int brow = (((lane >> 4) & 1) << 3) + (lane & 7);
    int bcol = (lane >> 3) & 1;
    uint32_t offA[2][4], offB[4][4];
#pragma unroll
    for (int mt = 0; mt < 2; mt++)
#pragma unroll
        for (int kki = 0; kki < 4; kki++)
            offA[mt][kki] = swb32(wm * 32 + mt * 16 + arow, kki * 2 + acol);
#pragma unroll
    for (int p = 0; p < 4; p++)
#pragma unroll
        for (int kki = 0; kki < 4; kki++)
            offB[p][kki] = swb32(wn * 64 + p * 16 + brow, kki * 2 + bcol);

    float acc[2][8][4] = {};

    auto compute_stage = [&](int s) {
        uint32_t base = sb + STG_BASE + s * STG_SZ;
        uint32_t aA = base, aB = base + 16384;
#pragma unroll
        for (int kki = 0; kki < 4; kki++) {
            uint32_t a[2][4];
            LDSM4(a[0][0], a[0][1], a[0][2], a[0][3], aA + offA[0][kki]);
            LDSM4(a[1][0], a[1][1], a[1][2], a[1][3], aA + offA[1][kki]);
#pragma unroll
            for (int p = 0; p < 4; p++) {
                uint32_t b[4];
                LDSM4(b[0], b[1], b[2], b[3], aB + offB[p][kki]);
#pragma unroll
                for (int mt = 0; mt < 2; mt++) {
                    mma8u(acc[mt][2 * p],     a[mt], &b[0]);
                    mma8u(acc[mt][2 * p + 1], a[mt], &b[2]);
                }
            }
        }
    };

    issue_stage(0, 0); CP_COMMIT();
    issue_stage(1, 1); CP_COMMIT();
#pragma unroll 1
    for (int kt = 0; kt < NKT2; kt++) {
        CP_WAIT1();
        __syncthreads();
        compute_stage(kt % 3);
        if (kt + 2 < NKT2) issue_stage((kt + 2) % 3, kt + 2);
        CP_COMMIT();
    }

    // epilogue: out[token, n] += cw * acc  (2 commutative adds/elem -> deterministic)
#pragma unroll
    for (int mt = 0; mt < 2; mt++) {
#pragma unroll
        for (int nt = 0; nt < 8; nt++) {
#pragma unroll
            for (int q = 0; q < 4; q++) {
                int r  = wm * 32 + mt * 16 + (lane >> 2) + ((q >= 2) ? 8 : 0);
                int cc = wn * 64 + nt * 8 + ((lane & 3) << 1) + (q & 1);
                int i = tile * 128 + r;
                if (i < cnt) {
                    int t  = stok[r];
                    float w = scw[r];
                    atomicAdd(&out[(size_t)t * DIM + n0 + cc], acc[mt][nt][q] * w);
                }
            }
        }
    }
}

// ---------------- launch ----------------
extern "C" void kernel_launch(void* const* d_in, const int* in_sizes, int n_in,
                              void* d_out, int out_size) {
    const float* x  = (const float*)d_in[0];
    const float* gw = (const float*)d_in[1];
    const float* w1 = (const float*)d_in[2];
    const float* w2 = (const float*)d_in[3];
    const float* w3 = (const float*)d_in[4];
    float* out = (float*)d_out;

    static bool attr_done = false;
    if (!attr_done) {
        cudaFuncSetAttribute(gemm1_kernel, cudaFuncAttributeMaxDynamicSharedMemorySize, SMEM_BYTES);
        cudaFuncSetAttribute(gemm2_kernel, cudaFuncAttributeMaxDynamicSharedMemorySize, SMEM_BYTES);
        attr_done = true;
    }

    float *xr, *w1r, *w2r, *w3r;
    cudaGetSymbolAddress((void**)&xr,  g_xr);
    cudaGetSymbolAddress((void**)&w1r, g_w1r);
    cudaGetSymbolAddress((void**)&w2r, g_w2r);
    cudaGetSymbolAddress((void**)&w3r, g_w3r);

    int nx4 = NTOK * DIM / 4, nw4 = NE * FF * DIM / 4;
    round_kernel<<<(nx4 + 255) / 256, 256>>>(x, xr, nx4);
    round_kernel<<<(nw4 + 255) / 256, 256>>>(w1, w1r, nw4);
    round_kernel<<<(nw4 + 255) / 256, 256>>>(w2, w2r, nw4);
    round_kernel<<<(nw4 + 255) / 256, 256>>>(w3, w3r, nw4);

    zero_kernel<<<(out_size + 255) / 256, 256>>>(out, out_size);
    gate_kernel<<<NTOK / 8, 256>>>(x, gw);
    prefix_kernel<<<1, 32>>>();
    gemm1_kernel<<<dim3(264, FF / 64), 256, SMEM_BYTES>>>();
    gemm2_kernel<<<dim3(264, DIM / 128), 256, SMEM_BYTES>>>(out);
}

// round 7
// speedup vs baseline: 1.0298x; 1.0298x over previous
#include <cuda_runtime.h>
#include <cstdint>
#include <math.h>

#define NE 8
#define NTOK 16384
#define DIM 1024
#define FF 2048

// ---------------- scratch (device globals; no allocation) ----------------
__device__ int   g_counts[NE];
__device__ int   g_offsets[NE + 1];
__device__ int   g_tok[NE * NTOK];
__device__ float g_cw[NE * NTOK];
__device__ float g_H[(size_t)2 * NTOK * FF];   // 256 MiB hidden activations

// ---------------- helpers ----------------
__device__ __forceinline__ unsigned f2tf(float f) {
    unsigned u;
    asm("cvt.rna.tf32.f32 %0, %1;" : "=r"(u) : "f"(f));
    return u;
}
__device__ __forceinline__ float f2tf_f(float f) { return __uint_as_float(f2tf(f)); }
__device__ __forceinline__ float4 cvt4(float4 v) {
    float4 r;
    r.x = f2tf_f(v.x); r.y = f2tf_f(v.y); r.z = f2tf_f(v.z); r.w = f2tf_f(v.w);
    return r;
}

static __device__ __forceinline__ uint32_t smem_u32(const void* p) {
    uint32_t a;
    asm("{ .reg .u64 t; cvta.to.shared.u64 t, %1; cvt.u32.u64 %0, t; }" : "=r"(a) : "l"(p));
    return a;
}

__device__ __forceinline__ void mma8u(float* c, const uint32_t* a, const uint32_t* b) {
    asm volatile(
        "mma.sync.aligned.m16n8k8.row.col.f32.tf32.tf32.f32 "
        "{%0,%1,%2,%3},{%4,%5,%6,%7},{%8,%9},{%0,%1,%2,%3};"
        : "+f"(c[0]), "+f"(c[1]), "+f"(c[2]), "+f"(c[3])
        : "r"(a[0]), "r"(a[1]), "r"(a[2]), "r"(a[3]), "r"(b[0]), "r"(b[1]));
}

#define LDSM4(r0_, r1_, r2_, r3_, addr)                                        \
    asm volatile("ldmatrix.sync.aligned.m8n8.x4.shared.b16 {%0,%1,%2,%3}, [%4];" \
        : "=r"(r0_), "=r"(r1_), "=r"(r2_), "=r"(r3_) : "r"(addr))

// Swizzled byte offset of 16B chunk: row r (64B rows = 16 floats), chunk base cb (0..3).
// chunk = cb ^ ((r>>1)&3): conflict-free STS.128 phases AND ldmatrix 8-row phases (verified).
__device__ __forceinline__ uint32_t swb(int r, int cb) {
    int chunk = (cb ^ (r >> 1)) & 3;
    return (uint32_t)(r * 64 + chunk * 16);
}

// ---------------- kernel 0: zero output + counts ----------------
__global__ void zero_kernel(float* out, int n) {
    int i = blockIdx.x * blockDim.x + threadIdx.x;
    if (i < n) out[i] = 0.0f;
    if (blockIdx.x == 0 && threadIdx.x < NE) g_counts[threadIdx.x] = 0;
}

// ---------------- kernel 1: gating + routing (one warp per token) ----------------
__global__ void gate_kernel(const float* __restrict__ x, const float* __restrict__ gw) {
    int warp = threadIdx.x >> 5;
    int lane = threadIdx.x & 31;
    int token = blockIdx.x * 8 + warp;

    const float* xr = x + (size_t)token * DIM;
    float xv[32];
#pragma unroll
    for (int j = 0; j < 32; j++) xv[j] = xr[j * 32 + lane];

    float logits[NE];
#pragma unroll
    for (int e = 0; e < NE; e++) {
        const float* g = gw + e * DIM;
        float s = 0.0f;
#pragma unroll
        for (int j = 0; j < 32; j++) s += xv[j] * g[j * 32 + lane];
#pragma unroll
        for (int o = 16; o; o >>= 1) s += __shfl_xor_sync(0xffffffffu, s, o);
        logits[e] = s;
    }

    if (lane == 0) {
        int i1 = 0;
#pragma unroll
        for (int e = 1; e < NE; e++)
            if (logits[e] > logits[i1]) i1 = e;
        int i2 = -1;
#pragma unroll
        for (int e = 0; e < NE; e++) {
            if (e == i1) continue;
            if (i2 < 0 || logits[e] > logits[i2]) i2 = e;
        }
        float p1 = 1.0f / (1.0f + __expf(logits[i2] - logits[i1]));
        float p2 = 1.0f - p1;
        int s1 = atomicAdd(&g_counts[i1], 1);
        g_tok[i1 * NTOK + s1] = token;
        g_cw[i1 * NTOK + s1]  = p1;
        int s2 = atomicAdd(&g_counts[i2], 1);
        g_tok[i2 * NTOK + s2] = token;
        g_cw[i2 * NTOK + s2]  = p2;
    }
}

// ---------------- kernel 2: prefix over 8 counts ----------------
__global__ void prefix_kernel() {
    if (threadIdx.x == 0) {
        int a = 0;
        for (int e = 0; e < NE; e++) { g_offsets[e] = a; a += g_counts[e]; }
        g_offsets[NE] = a;
    }
}

// ---------------- tile scheduler ----------------
__device__ __forceinline__ bool find_tile(int bx, int& e, int& tile, int& cnt) {
    int acc = 0;
    e = -1;
#pragma unroll
    for (int ee = 0; ee < NE; ee++) {
        int c = g_counts[ee];
        int t = (c + 127) >> 7;
        if (e < 0 && bx < acc + t) { e = ee; tile = bx - acc; cnt = c; }
        acc += t;
    }
    return e >= 0;
}

// dynamic SMEM: [0:512) stok, [512:1024) scw, stages at 1024 + s*24576
#define STG_BASE 1024
#define STG_SZ   24576
#define SMEM_BYTES (STG_BASE + 2 * STG_SZ)

// ---------------- kernel 3: GEMM1 (x@w1^T, x@w3^T) -> silu*mul -> H ----------------
// BM=128, BN=128 per matrix (dual), BK=16; warps 2Mx4N, warp tile 64x32 per matrix
__global__ __launch_bounds__(256, 1) void gemm1_kernel(const float* __restrict__ x,
                                                       const float* __restrict__ w1,
                                                       const float* __restrict__ w3) {
    extern __shared__ char dsm[];
    int e, tile, cnt;
    if (!find_tile(blockIdx.x, e, tile, cnt)) return;
    int offs = g_offsets[e];
    int n0 = blockIdx.y * 128;

    int tid = threadIdx.x;
    int* stok = (int*)dsm;
    if (tid < 128) {
        int i = tile * 128 + tid;
        stok[tid] = (i < cnt) ? g_tok[e * NTOK + i] : -1;
    }
    __syncthreads();

    int warp = tid >> 5, lane = tid & 31;
    int wm = warp >> 2, wn = warp & 3;          // 2M x 4N
    uint32_t sb = smem_u32(dsm);

    // ---- global load coordinates: A/B1/B3 each 128x16 = 512 float4, 2/thread ----
    int ar[2], acb[2];
    const float* ap[2]; bool avA[2];
    const float* b1p[2]; const float* b3p[2];
    uint32_t sto[2];
#pragma unroll
    for (int j = 0; j < 2; j++) {
        int idx = tid + j * 256;
        ar[j]  = idx >> 2;
        acb[j] = idx & 3;
        sto[j] = swb(ar[j], acb[j]);
        int t = stok[ar[j]];
        avA[j] = (t >= 0);
        ap[j]  = x + (size_t)(t < 0 ? 0 : t) * DIM + acb[j] * 4;
        b1p[j] = w1 + (size_t)e * FF * DIM + (size_t)(n0 + ar[j]) * DIM + acb[j] * 4;
        b3p[j] = w3 + (size_t)e * FF * DIM + (size_t)(n0 + ar[j]) * DIM + acb[j] * 4;
    }

    // ---- ldmatrix fragment offsets ----
    int arow = (((lane >> 3) & 1) << 3) + (lane & 7);
    int acol = lane >> 4;
    int brow = (((lane >> 4) & 1) << 3) + (lane & 7);
    int bcol = (lane >> 3) & 1;
    uint32_t offA[4][2], offB[2][2];
#pragma unroll
    for (int mt = 0; mt < 4; mt++)
#pragma unroll
        for (int kki = 0; kki < 2; kki++)
            offA[mt][kki] = swb(wm * 64 + mt * 16 + arow, kki * 2 + acol);
#pragma unroll
    for (int p = 0; p < 2; p++)
#pragma unroll
        for (int kki = 0; kki < 2; kki++)
            offB[p][kki] = swb(wn * 32 + p * 16 + brow, kki * 2 + bcol);

    float4 ra[2], rb1[2], rb3[2];
    auto load_k = [&](int k0) {
#pragma unroll
        for (int j = 0; j < 2; j++) {
            ra[j]  = avA[j] ? *(const float4*)(ap[j] + k0) : make_float4(0.f, 0.f, 0.f, 0.f);
            rb1[j] = *(const float4*)(b1p[j] + k0);
            rb3[j] = *(const float4*)(b3p[j] + k0);
        }
    };
    auto store_stage = [&](int s) {
        char* base = dsm + STG_BASE + s * STG_SZ;
#pragma unroll
        for (int j = 0; j < 2; j++) {
            *(float4*)(base + sto[j])         = cvt4(ra[j]);
            *(float4*)(base + 8192 + sto[j])  = cvt4(rb1[j]);
            *(float4*)(base + 16384 + sto[j]) = cvt4(rb3[j]);
        }
    };

    float acc1[4][4][4] = {};
    float acc3[4][4][4] = {};

    auto compute_stage = [&](int s) {
        uint32_t base = sb + STG_BASE + s * STG_SZ;
        uint32_t aA = base, aB1 = base + 8192, aB3 = base + 16384;
#pragma unroll
        for (int kki = 0; kki < 2; kki++) {
            uint32_t a[4][4];
#pragma unroll
            for (int mt = 0; mt < 4; mt++)
                LDSM4(a[mt][0], a[mt][1], a[mt][2], a[mt][3], aA + offA[mt][kki]);
#pragma unroll
            for (int p = 0; p < 2; p++) {
                uint32_t b1[4], b3[4];
                LDSM4(b1[0], b1[1], b1[2], b1[3], aB1 + offB[p][kki]);
                LDSM4(b3[0], b3[1], b3[2], b3[3], aB3 + offB[p][kki]);
#pragma unroll
                for (int mt = 0; mt < 4; mt++) {
                    mma8u(acc1[mt][2 * p],     a[mt], &b1[0]);
                    mma8u(acc1[mt][2 * p + 1], a[mt], &b1[2]);
                    mma8u(acc3[mt][2 * p],     a[mt], &b3[0]);
                    mma8u(acc3[mt][2 * p + 1], a[mt], &b3[2]);
                }
            }
        }
    };

    load_k(0);
    store_stage(0);
    __syncthreads();
#pragma unroll 1
    for (int kt = 0; kt < DIM / 16; kt++) {
        int cur = kt & 1;
        if (kt + 1 < DIM / 16) load_k((kt + 1) * 16);
        compute_stage(cur);
        if (kt + 1 < DIM / 16) store_stage(cur ^ 1);
        __syncthreads();
    }

    // epilogue: h = silu(s1) * s3 -> g_H
#pragma unroll
    for (int mt = 0; mt < 4; mt++) {
#pragma unroll
        for (int nt = 0; nt < 4; nt++) {
#pragma unroll
            for (int q = 0; q < 4; q++) {
                int r  = wm * 64 + mt * 16 + (lane >> 2) + ((q >= 2) ? 8 : 0);
                int cc = wn * 32 + nt * 8 + ((lane & 3) << 1) + (q & 1);
                int i = tile * 128 + r;
                if (i < cnt) {
                    float s1 = acc1[mt][nt][q], s3 = acc3[mt][nt][q];
                    float h = (s1 / (1.0f + __expf(-s1))) * s3;
                    g_H[(size_t)(offs + i) * FF + n0 + cc] = h;
                }
            }
        }
    }
}

// ---------------- kernel 4: GEMM2 (H @ w2^T), BN=256, scaled scatter-add ----------------
// warps 2Mx4N, warp tile 64x64
__global__ __launch_bounds__(256, 1) void gemm2_kernel(const float* __restrict__ w2,
                                                       float* __restrict__ out) {
    extern __shared__ char dsm[];
    int e, tile, cnt;
    if (!find_tile(blockIdx.x, e, tile, cnt)) return;
    int offs = g_offsets[e];
    int n0 = blockIdx.y * 256;

    int tid = threadIdx.x;
    int*   stok = (int*)dsm;
    float* scw  = (float*)(dsm + 512);
    if (tid < 128) {
        int i = tile * 128 + tid;
        stok[tid] = (i < cnt) ? g_tok[e * NTOK + i] : -1;
        scw[tid]  = (i < cnt) ? g_cw[e * NTOK + i] : 0.0f;
    }
    __syncthreads();

    int warp = tid >> 5, lane = tid & 31;
    int wm = warp >> 2, wn = warp & 3;
    uint32_t sb = smem_u32(dsm);

    // A: 128x16 = 512 float4 (2/thread); B: 256x16 = 1024 float4 (4/thread)
    int ar[2], acb[2]; uint32_t stoA[2]; const float* ap[2]; bool avA[2];
#pragma unroll
    for (int j = 0; j < 2; j++) {
        int idx = tid + j * 256;
        ar[j]  = idx >> 2;
        acb[j] = idx & 3;
        stoA[j] = swb(ar[j], acb[j]);
        bool av = (tile * 128 + ar[j]) < cnt;
        avA[j] = av;
        ap[j] = g_H + (size_t)(offs + tile * 128 + (av ? ar[j] : 0)) * FF + acb[j] * 4;
    }
    uint32_t stoB[4]; const float* bp[4];
#pragma unroll
    for (int j = 0; j < 4; j++) {
        int idx = tid + j * 256;
        int r = idx >> 2, c = idx & 3;
        stoB[j] = swb(r, c);
        bp[j] = w2 + (size_t)e * DIM * FF + (size_t)(n0 + r) * FF + c * 4;
    }

    int arow = (((lane >> 3) & 1) << 3) + (lane & 7);
    int acol = lane >> 4;
    int brow = (((lane >> 4) & 1) << 3) + (lane & 7);
    int bcol = (lane >> 3) & 1;
    uint32_t offA[4][2], offB[4][2];
#pragma unroll
    for (int mt = 0; mt < 4; mt++)
#pragma unroll
        for (int kki = 0; kki < 2; kki++)
            offA[mt][kki] = swb(wm * 64 + mt * 16 + arow, kki * 2 + acol);
#pragma unroll
    for (int p = 0; p < 4; p++)
#pragma unroll
        for (int kki = 0; kki < 2; kki++)
            offB[p][kki] = swb(wn * 64 + p * 16 + brow, kki * 2 + bcol);

    float4 ra[2], rb[4];
    auto load_k = [&](int k0) {
#pragma unroll
        for (int j = 0; j < 2; j++)
            ra[j] = avA[j] ? *(const float4*)(ap[j] + k0) : make_float4(0.f, 0.f, 0.f, 0.f);
#pragma unroll
        for (int j = 0; j < 4; j++)
            rb[j] = *(const float4*)(bp[j] + k0);
    };
    auto store_stage = [&](int s) {
        char* base = dsm + STG_BASE + s * STG_SZ;
#pragma unroll
        for (int j = 0; j < 2; j++)
            *(float4*)(base + stoA[j]) = cvt4(ra[j]);
#pragma unroll
        for (int j = 0; j < 4; j++)
            *(float4*)(base + 8192 + stoB[j]) = cvt4(rb[j]);
    };

    float acc[4][8][4] = {};

    auto compute_stage = [&](int s) {
        uint32_t base = sb + STG_BASE + s * STG_SZ;
        uint32_t aA = base, aB = base + 8192;
#pragma unroll
        for (int kki = 0; kki < 2; kki++) {
            uint32_t a[4][4];
#pragma unroll
            for (int mt = 0; mt < 4; mt++)
                LDSM4(a[mt][0], a[mt][1], a[mt][2], a[mt][3], aA + offA[mt][kki]);
#pragma unroll
            for (int p = 0; p < 4; p++) {
                uint32_t b[4];
                LDSM4(b[0], b[1], b[2], b[3], aB + offB[p][kki]);
#pragma unroll
                for (int mt = 0; mt < 4; mt++) {
                    mma8u(acc[mt][2 * p],     a[mt], &b[0]);
                    mma8u(acc[mt][2 * p + 1], a[mt], &b[2]);
                }
            }
        }
    };

    load_k(0);
    store_stage(0);
    __syncthreads();
#pragma unroll 1
    for (int kt = 0; kt < FF / 16; kt++) {
        int cur = kt & 1;
        if (kt + 1 < FF / 16) load_k((kt + 1) * 16);
        compute_stage(cur);
        if (kt + 1 < FF / 16) store_stage(cur ^ 1);
        __syncthreads();
    }

    // epilogue: out[token, n] += cw * acc  (2 commutative adds/elem -> deterministic)
#pragma unroll
    for (int mt = 0; mt < 4; mt++) {
#pragma unroll
        for (int nt = 0; nt < 8; nt++) {
#pragma unroll
            for (int q = 0; q < 4; q++) {
                int r  = wm * 64 + mt * 16 + (lane >> 2) + ((q >= 2) ? 8 : 0);
                int cc = wn * 64 + nt * 8 + ((lane & 3) << 1) + (q & 1);
                int i = tile * 128 + r;
                if (i < cnt) {
                    int t  = stok[r];
                    float w = scw[r];
                    atomicAdd(&out[(size_t)t * DIM + n0 + cc], acc[mt][nt][q] * w);
                }
            }
        }
    }
}

// ---------------- launch ----------------
extern "C" void kernel_launch(void* const* d_in, const int* in_sizes, int n_in,
                              void* d_out, int out_size) {
    const float* x  = (const float*)d_in[0];
    const float* gw = (const float*)d_in[1];
    const float* w1 = (const float*)d_in[2];
    const float* w2 = (const float*)d_in[3];
    const float* w3 = (const float*)d_in[4];
    float* out = (float*)d_out;

    cudaFuncSetAttribute(gemm1_kernel, cudaFuncAttributeMaxDynamicSharedMemorySize, SMEM_BYTES);
    cudaFuncSetAttribute(gemm2_kernel, cudaFuncAttributeMaxDynamicSharedMemorySize, SMEM_BYTES);

    zero_kernel<<<(out_size + 255) / 256, 256>>>(out, out_size);
    gate_kernel<<<NTOK / 8, 256>>>(x, gw);
    prefix_kernel<<<1, 32>>>();
    gemm1_kernel<<<dim3(264, FF / 128), 256, SMEM_BYTES>>>(x, w1, w3);
    gemm2_kernel<<<dim3(264, DIM / 256), 256, SMEM_BYTES>>>(w2, out);
}

// round 8
// speedup vs baseline: 1.7930x; 1.7411x over previous
#include <cuda_runtime.h>
#include <cuda_fp16.h>
#include <cstdint>
#include <math.h>

#define NE 8
#define NTOK 16384
#define DIM 1024
#define FF 2048
#define NKT1 (DIM / 32)
#define NKT2 (FF / 32)

// ---------------- scratch (device globals; no allocation) ----------------
__device__ int    g_counts[NE];
__device__ int    g_offsets[NE + 1];
__device__ int    g_tok[NE * NTOK];
__device__ float  g_cw[NE * NTOK];
__device__ __half g_H[(size_t)2 * NTOK * FF];   // 128 MiB hidden activations (fp16)

// ---------------- helpers ----------------
__device__ __forceinline__ uint32_t ph2(float a, float b) {
    __half2 h = __floats2half2_rn(a, b);
    return *(uint32_t*)&h;
}
__device__ __forceinline__ uint4 pack8(float4 lo, float4 hi) {
    uint4 u;
    u.x = ph2(lo.x, lo.y); u.y = ph2(lo.z, lo.w);
    u.z = ph2(hi.x, hi.y); u.w = ph2(hi.z, hi.w);
    return u;
}

static __device__ __forceinline__ uint32_t smem_u32(const void* p) {
    uint32_t a;
    asm("{ .reg .u64 t; cvta.to.shared.u64 t, %1; cvt.u32.u64 %0, t; }" : "=r"(a) : "l"(p));
    return a;
}

__device__ __forceinline__ void mma16(float* c, const uint32_t* a, const uint32_t* b) {
    asm volatile(
        "mma.sync.aligned.m16n8k16.row.col.f32.f16.f16.f32 "
        "{%0,%1,%2,%3},{%4,%5,%6,%7},{%8,%9},{%0,%1,%2,%3};"
        : "+f"(c[0]), "+f"(c[1]), "+f"(c[2]), "+f"(c[3])
        : "r"(a[0]), "r"(a[1]), "r"(a[2]), "r"(a[3]), "r"(b[0]), "r"(b[1]));
}

#define LDSM4(r0_, r1_, r2_, r3_, addr)                                        \
    asm volatile("ldmatrix.sync.aligned.m8n8.x4.shared.b16 {%0,%1,%2,%3}, [%4];" \
        : "=r"(r0_), "=r"(r1_), "=r"(r2_), "=r"(r3_) : "r"(addr))

// Swizzled byte offset: row r (64B rows = 32 halfs), 16B chunk cb (0..3).
// chunk = cb ^ ((r>>1)&3): conflict-free STS.128 phases AND ldmatrix 8-row phases (verified).
__device__ __forceinline__ uint32_t swb(int r, int cb) {
    int chunk = (cb ^ (r >> 1)) & 3;
    return (uint32_t)(r * 64 + chunk * 16);
}

// ---------------- kernel 0: zero output + counts ----------------
__global__ void zero_kernel(float* out, int n) {
    int i = blockIdx.x * blockDim.x + threadIdx.x;
    if (i < n) out[i] = 0.0f;
    if (blockIdx.x == 0 && threadIdx.x < NE) g_counts[threadIdx.x] = 0;
}

// ---------------- kernel 1: gating + routing (one warp per token) ----------------
__global__ void gate_kernel(const float* __restrict__ x, const float* __restrict__ gw) {
    int warp = threadIdx.x >> 5;
    int lane = threadIdx.x & 31;
    int token = blockIdx.x * 8 + warp;

    const float* xr = x + (size_t)token * DIM;
    float xv[32];
#pragma unroll
    for (int j = 0; j < 32; j++) xv[j] = xr[j * 32 + lane];

    float logits[NE];
#pragma unroll
    for (int e = 0; e < NE; e++) {
        const float* g = gw + e * DIM;
        float s = 0.0f;
#pragma unroll
        for (int j = 0; j < 32; j++) s += xv[j] * g[j * 32 + lane];
#pragma unroll
        for (int o = 16; o; o >>= 1) s += __shfl_xor_sync(0xffffffffu, s, o);
        logits[e] = s;
    }

    if (lane == 0) {
        int i1 = 0;
#pragma unroll
        for (int e = 1; e < NE; e++)
            if (logits[e] > logits[i1]) i1 = e;
        int i2 = -1;
#pragma unroll
        for (int e = 0; e < NE; e++) {
            if (e == i1) continue;
            if (i2 < 0 || logits[e] > logits[i2]) i2 = e;
        }
        float p1 = 1.0f / (1.0f + __expf(logits[i2] - logits[i1]));
        float p2 = 1.0f - p1;
        int s1 = atomicAdd(&g_counts[i1], 1);
        g_tok[i1 * NTOK + s1] = token;
        g_cw[i1 * NTOK + s1]  = p1;
        int s2 = atomicAdd(&g_counts[i2], 1);
        g_tok[i2 * NTOK + s2] = token;
        g_cw[i2 * NTOK + s2]  = p2;
    }
}

// ---------------- kernel 2: prefix over 8 counts ----------------
__global__ void prefix_kernel() {
    if (threadIdx.x == 0) {
        int a = 0;
        for (int e = 0; e < NE; e++) { g_offsets[e] = a; a += g_counts[e]; }
        g_offsets[NE] = a;
    }
}

// ---------------- tile scheduler ----------------
__device__ __forceinline__ bool find_tile(int bx, int& e, int& tile, int& cnt) {
    int acc = 0;
    e = -1;
#pragma unroll
    for (int ee = 0; ee < NE; ee++) {
        int c = g_counts[ee];
        int t = (c + 127) >> 7;
        if (e < 0 && bx < acc + t) { e = ee; tile = bx - acc; cnt = c; }
        acc += t;
    }
    return e >= 0;
}

// ---------------- kernel 3: GEMM1 (x@w1^T, x@w3^T) -> silu*mul -> H(fp16) ----------------
// BM=128, BN=64 (dual B), BK=32 halfs; double-buffered, fp16 SMEM, LDSM operand path
__global__ __launch_bounds__(256, 2) void gemm1_kernel(const float* __restrict__ x,
                                                       const float* __restrict__ w1,
                                                       const float* __restrict__ w3) {
    __shared__ __align__(16) char smA[2][8192];
    __shared__ __align__(16) char smB1[2][4096];
    __shared__ __align__(16) char smB3[2][4096];
    __shared__ int stok[128];

    int e, tile, cnt;
    if (!find_tile(blockIdx.x, e, tile, cnt)) return;
    int offs = g_offsets[e];
    int n0 = blockIdx.y * 64;

    int tid = threadIdx.x;
    if (tid < 128) {
        int i = tile * 128 + tid;
        stok[tid] = (i < cnt) ? g_tok[e * NTOK + i] : -1;
    }
    __syncthreads();

    int warp = tid >> 5, lane = tid & 31;
    int wm = warp >> 1, wn = warp & 1;      // 4M x 2N warps, warp tile 32x32 per matrix

    // ---- global load coordinates (32 fp32 per row per tile; thread = 16B-half-chunk) ----
    int hc = tid & 3;                        // chunk 0..3 -> float col hc*8
    int arr[2]; bool avA[2]; const float* ap[2]; uint32_t stoA[2];
#pragma unroll
    for (int j = 0; j < 2; j++) {
        int idx = tid + j * 256;
        arr[j]  = idx >> 2;                  // A rows 0..63, 64..127
        stoA[j] = swb(arr[j], hc);
        int t = stok[arr[j]];
        avA[j] = (t >= 0);
        ap[j]  = x + (size_t)(t < 0 ? 0 : t) * DIM + hc * 8;
    }
    int br = tid >> 2;                       // B rows 0..63
    uint32_t stoB = swb(br, hc);
    const float* b1p = w1 + (size_t)e * FF * DIM + (size_t)(n0 + br) * DIM + hc * 8;
    const float* b3p = w3 + (size_t)e * FF * DIM + (size_t)(n0 + br) * DIM + hc * 8;

    // ---- ldmatrix fragment offsets (hoisted) ----
    int arow = (((lane >> 3) & 1) << 3) + (lane & 7);
    int acol = lane >> 4;
    int brow = (((lane >> 4) & 1) << 3) + (lane & 7);
    int bcol = (lane >> 3) & 1;
    uint32_t offA[2][2], offB[2][2];
#pragma unroll
    for (int mt = 0; mt < 2; mt++)
#pragma unroll
        for (int kki = 0; kki < 2; kki++)
            offA[mt][kki] = swb(wm * 32 + mt * 16 + arow, kki * 2 + acol);
#pragma unroll
    for (int p = 0; p < 2; p++)
#pragma unroll
        for (int kki = 0; kki < 2; kki++)
            offB[p][kki] = swb(wn * 32 + p * 16 + brow, kki * 2 + bcol);

    float4 ra[2][2], rb1[2], rb3[2];
    auto load_k = [&](int k0) {
#pragma unroll
        for (int j = 0; j < 2; j++) {
            ra[j][0] = avA[j] ? *(const float4*)(ap[j] + k0)     : make_float4(0.f, 0.f, 0.f, 0.f);
            ra[j][1] = avA[j] ? *(const float4*)(ap[j] + k0 + 4) : make_float4(0.f, 0.f, 0.f, 0.f);
        }
        rb1[0] = *(const float4*)(b1p + k0); rb1[1] = *(const float4*)(b1p + k0 + 4);
        rb3[0] = *(const float4*)(b3p + k0); rb3[1] = *(const float4*)(b3p + k0 + 4);
    };
    auto store_stage = [&](int s) {
#pragma unroll
        for (int j = 0; j < 2; j++)
            *(uint4*)(smA[s] + stoA[j]) = pack8(ra[j][0], ra[j][1]);
        *(uint4*)(smB1[s] + stoB) = pack8(rb1[0], rb1[1]);
        *(uint4*)(smB3[s] + stoB) = pack8(rb3[0], rb3[1]);
    };

    float acc1[2][4][4] = {};
    float acc3[2][4][4] = {};

    auto compute_stage = [&](int s) {
        uint32_t aA  = smem_u32(smA[s]);
        uint32_t aB1 = smem_u32(smB1[s]);
        uint32_t aB3 = smem_u32(smB3[s]);
#pragma unroll
        for (int kki = 0; kki < 2; kki++) {
            uint32_t a[2][4];
            LDSM4(a[0][0], a[0][1], a[0][2], a[0][3], aA + offA[0][kki]);
            LDSM4(a[1][0], a[1][1], a[1][2], a[1][3], aA + offA[1][kki]);
#pragma unroll
            for (int p = 0; p < 2; p++) {
                uint32_t b1[4], b3[4];
                LDSM4(b1[0], b1[1], b1[2], b1[3], aB1 + offB[p][kki]);
                LDSM4(b3[0], b3[1], b3[2], b3[3], aB3 + offB[p][kki]);
#pragma unroll
                for (int mt = 0; mt < 2; mt++) {
                    mma16(acc1[mt][2 * p],     a[mt], &b1[0]);
                    mma16(acc1[mt][2 * p + 1], a[mt], &b1[2]);
                    mma16(acc3[mt][2 * p],     a[mt], &b3[0]);
                    mma16(acc3[mt][2 * p + 1], a[mt], &b3[2]);
                }
            }
        }
    };

    load_k(0);
    store_stage(0);
    __syncthreads();
#pragma unroll 1
    for (int kt = 0; kt < NKT1; kt++) {
        int cur = kt & 1;
        if (kt + 1 < NKT1) load_k((kt + 1) * 32);
        compute_stage(cur);
        if (kt + 1 < NKT1) store_stage(cur ^ 1);
        __syncthreads();
    }

    // epilogue: h = silu(s1) * s3 -> g_H (fp16, half2 stores)
#pragma unroll
    for (int mt = 0; mt < 2; mt++) {
#pragma unroll
        for (int nt = 0; nt < 4; nt++) {
            int r0 = wm * 32 + mt * 16 + (lane >> 2);
            int cc = wn * 32 + nt * 8 + ((lane & 3) << 1);
#pragma unroll
            for (int h8 = 0; h8 < 2; h8++) {   // row r0, r0+8
                int i = tile * 128 + r0 + h8 * 8;
                if (i < cnt) {
                    float s1a = acc1[mt][nt][2 * h8],     s3a = acc3[mt][nt][2 * h8];
                    float s1b = acc1[mt][nt][2 * h8 + 1], s3b = acc3[mt][nt][2 * h8 + 1];
                    float ha = (s1a / (1.0f + __expf(-s1a))) * s3a;
                    float hb = (s1b / (1.0f + __expf(-s1b))) * s3b;
                    *(__half2*)(g_H + (size_t)(offs + i) * FF + n0 + cc) =
                        __floats2half2_rn(ha, hb);
                }
            }
        }
    }
}

// ---------------- kernel 4: GEMM2 (H @ w2^T), BN=128, scaled scatter-add ----------------
__global__ __launch_bounds__(256, 2) void gemm2_kernel(const float* __restrict__ w2,
                                                       float* __restrict__ out) {
    __shared__ __align__(16) char smA[2][8192];
    __shared__ __align__(16) char smB[2][8192];
    __shared__ int   stok[128];
    __shared__ float scw[128];

    int e, tile, cnt;
    if (!find_tile(blockIdx.x, e, tile, cnt)) return;
    int offs = g_offsets[e];
    int n0 = blockIdx.y * 128;

    int tid = threadIdx.x;
    if (tid < 128) {
        int i = tile * 128 + tid;
        stok[tid] = (i < cnt) ? g_tok[e * NTOK + i] : -1;
        scw[tid]  = (i < cnt) ? g_cw[e * NTOK + i] : 0.0f;
    }
    __syncthreads();

    int warp = tid >> 5, lane = tid & 31;
    int wm = warp >> 1, wn = warp & 1;      // 4M x 2N warps, warp tile 32x64

    int hc = tid & 3;
    // A (fp16 from g_H): 2 chunk-rows/thread, direct 16B loads, no cvt
    int arr[2]; bool avA[2]; const __half* apH[2]; uint32_t stoA[2];
#pragma unroll
    for (int j = 0; j < 2; j++) {
        int idx = tid + j * 256;
        arr[j]  = idx >> 2;
        stoA[j] = swb(arr[j], hc);
        bool av = (tile * 128 + arr[j]) < cnt;
        avA[j] = av;
        apH[j] = g_H + (size_t)(offs + tile * 128 + (av ? arr[j] : 0)) * FF + hc * 8;
    }
    // B (fp32 w2): 128 rows x 4 chunks = 512 chunks = 2/thread
    int brr[2]; const float* bp[2]; uint32_t stoB[2];
#pragma unroll
    for (int j = 0; j < 2; j++) {
        int idx = tid + j * 256;
        brr[j]  = idx >> 2;
        stoB[j] = swb(brr[j], hc);
        bp[j]   = w2 + (size_t)e * DIM * FF + (size_t)(n0 + brr[j]) * FF + hc * 8;
    }

    int arow = (((lane >> 3) & 1) << 3) + (lane & 7);
    int acol = lane >> 4;
    int brow = (((lane >> 4) & 1) << 3) + (lane & 7);
    int bcol = (lane >> 3) & 1;
    uint32_t offA[2][2], offB[4][2];
#pragma unroll
    for (int mt = 0; mt < 2; mt++)
#pragma unroll
        for (int kki = 0; kki < 2; kki++)
            offA[mt][kki] = swb(wm * 32 + mt * 16 + arow, kki * 2 + acol);
#pragma unroll
    for (int p = 0; p < 4; p++)
#pragma unroll
        for (int kki = 0; kki < 2; kki++)
            offB[p][kki] = swb(wn * 64 + p * 16 + brow, kki * 2 + bcol);

    uint4 raH[2]; float4 rbf[2][2];
    auto load_k = [&](int kt) {
#pragma unroll
        for (int j = 0; j < 2; j++)
            raH[j] = avA[j] ? *(const uint4*)(apH[j] + kt * 32) : make_uint4(0u, 0u, 0u, 0u);
#pragma unroll
        for (int j = 0; j < 2; j++) {
            rbf[j][0] = *(const float4*)(bp[j] + kt * 32);
            rbf[j][1] = *(const float4*)(bp[j] + kt * 32 + 4);
        }
    };
    auto store_stage = [&](int s) {
#pragma unroll
        for (int j = 0; j < 2; j++)
            *(uint4*)(smA[s] + stoA[j]) = raH[j];
#pragma unroll
        for (int j = 0; j < 2; j++)
            *(uint4*)(smB[s] + stoB[j]) = pack8(rbf[j][0], rbf[j][1]);
    };

    float acc[2][8][4] = {};

    auto compute_stage = [&](int s) {
        uint32_t aA = smem_u32(smA[s]);
        uint32_t aB = smem_u32(smB[s]);
#pragma unroll
        for (int kki = 0; kki < 2; kki++) {
            uint32_t a[2][4];
            LDSM4(a[0][0], a[0][1], a[0][2], a[0][3], aA + offA[0][kki]);
            LDSM4(a[1][0], a[1][1], a[1][2], a[1][3], aA + offA[1][kki]);
#pragma unroll
            for (int p = 0; p < 4; p++) {
                uint32_t b[4];
                LDSM4(b[0], b[1], b[2], b[3], aB + offB[p][kki]);
#pragma unroll
                for (int mt = 0; mt < 2; mt++) {
                    mma16(acc[mt][2 * p],     a[mt], &b[0]);
                    mma16(acc[mt][2 * p + 1], a[mt], &b[2]);
                }
            }
        }
    };

    load_k(0);
    store_stage(0);
    __syncthreads();
#pragma unroll 1
    for (int kt = 0; kt < NKT2; kt++) {
        int cur = kt & 1;
        if (kt + 1 < NKT2) load_k(kt + 1);
        compute_stage(cur);
        if (kt + 1 < NKT2) store_stage(cur ^ 1);
        __syncthreads();
    }

    // epilogue: out[token, n] += cw * acc  (2 commutative adds/elem -> deterministic)
#pragma unroll
    for (int mt = 0; mt < 2; mt++) {
#pragma unroll
        for (int nt = 0; nt < 8; nt++) {
#pragma unroll
            for (int q = 0; q < 4; q++) {
                int r  = wm * 32 + mt * 16 + (lane >> 2) + ((q >= 2) ? 8 : 0);
                int cc = wn * 64 + nt * 8 + ((lane & 3) << 1) + (q & 1);
                int i = tile * 128 + r;
                if (i < cnt) {
                    int t  = stok[r];
                    float w = scw[r];
                    atomicAdd(&out[(size_t)t * DIM + n0 + cc], acc[mt][nt][q] * w);
                }
            }
        }
    }
}

// ---------------- launch ----------------
extern "C" void kernel_launch(void* const* d_in, const int* in_sizes, int n_in,
                              void* d_out, int out_size) {
    const float* x  = (const float*)d_in[0];
    const float* gw = (const float*)d_in[1];
    const float* w1 = (const float*)d_in[2];
    const float* w2 = (const float*)d_in[3];
    const float* w3 = (const float*)d_in[4];
    float* out = (float*)d_out;

    zero_kernel<<<(out_size + 255) / 256, 256>>>(out, out_size);
    gate_kernel<<<NTOK / 8, 256>>>(x, gw);
    prefix_kernel<<<1, 32>>>();
    gemm1_kernel<<<dim3(264, FF / 64), 256>>>(x, w1, w3);
    gemm2_kernel<<<dim3(264, DIM / 128), 256>>>(w2, out);
}

// round 9
// speedup vs baseline: 2.5918x; 1.4455x over previous
#include <cuda_runtime.h>
#include <cuda_fp16.h>
#include <cstdint>
#include <math.h>

#define NE 8
#define NTOK 16384
#define DIM 1024
#define FF 2048
#define NKT1 (DIM / 64)
#define NKT2 (FF / 64)

// ---------------- scratch (device globals; no allocation) ----------------
__device__ int    g_counts[NE];
__device__ int    g_offsets[NE + 1];
__device__ int    g_tok[NE * NTOK];
__device__ float  g_cw[NE * NTOK];
__device__ __half g_H[(size_t)2 * NTOK * FF];        // hidden activations (fp16)
__device__ __half g_xh[(size_t)NTOK * DIM];          // fp16 x
__device__ __half g_w1h[(size_t)NE * FF * DIM];      // fp16 w1
__device__ __half g_w2h[(size_t)NE * DIM * FF];      // fp16 w2
__device__ __half g_w3h[(size_t)NE * FF * DIM];      // fp16 w3

// ---------------- helpers ----------------
__device__ __forceinline__ uint32_t ph2(float a, float b) {
    __half2 h = __floats2half2_rn(a, b);
    return *(uint32_t*)&h;
}

static __device__ __forceinline__ uint32_t smem_u32(const void* p) {
    uint32_t a;
    asm("{ .reg .u64 t; cvta.to.shared.u64 t, %1; cvt.u32.u64 %0, t; }" : "=r"(a) : "l"(p));
    return a;
}

__device__ __forceinline__ void mma16(float* c, const uint32_t* a, const uint32_t* b) {
    asm volatile(
        "mma.sync.aligned.m16n8k16.row.col.f32.f16.f16.f32 "
        "{%0,%1,%2,%3},{%4,%5,%6,%7},{%8,%9},{%0,%1,%2,%3};"
        : "+f"(c[0]), "+f"(c[1]), "+f"(c[2]), "+f"(c[3])
        : "r"(a[0]), "r"(a[1]), "r"(a[2]), "r"(a[3]), "r"(b[0]), "r"(b[1]));
}

#define LDSM4(r0_, r1_, r2_, r3_, addr)                                        \
    asm volatile("ldmatrix.sync.aligned.m8n8.x4.shared.b16 {%0,%1,%2,%3}, [%4];" \
        : "=r"(r0_), "=r"(r1_), "=r"(r2_), "=r"(r3_) : "r"(addr))

__device__ __forceinline__ void cpa16(uint32_t dst, const void* src, uint32_t nbytes) {
    asm volatile("cp.async.cg.shared.global [%0], [%1], 16, %2;"
                 :: "r"(dst), "l"(src), "r"(nbytes) : "memory");
}
#define CP_COMMIT() asm volatile("cp.async.commit_group;" ::: "memory")
#define CP_WAIT1()  asm volatile("cp.async.wait_group 1;" ::: "memory")

// 128B-row swizzle (64 halfs/row): row r, 16B chunk c (0..7) -> phys chunk c^(r&7).
// ldmatrix phase = 8 consecutive rows at fixed c -> 8 distinct chunks: conflict-free.
__device__ __forceinline__ uint32_t swb32(int r, int c) {
    return (uint32_t)(r * 128 + ((c ^ r) & 7) * 16);
}

// ---------------- prepass: fp32 -> fp16 ----------------
__global__ void tohalf_kernel(const float* __restrict__ src, __half* __restrict__ dst, int n4) {
    int i = blockIdx.x * blockDim.x + threadIdx.x;
    if (i < n4) {
        float4 v = ((const float4*)src)[i];
        uint2 u;
        u.x = ph2(v.x, v.y);
        u.y = ph2(v.z, v.w);
        ((uint2*)dst)[i] = u;
    }
}

// ---------------- kernel 0: zero output + counts ----------------
__global__ void zero_kernel(float* out, int n) {
    int i = blockIdx.x * blockDim.x + threadIdx.x;
    if (i < n) out[i] = 0.0f;
    if (blockIdx.x == 0 && threadIdx.x < NE) g_counts[threadIdx.x] = 0;
}

// ---------------- kernel 1: gating + routing (one warp per token) ----------------
__global__ void gate_kernel(const float* __restrict__ x, const float* __restrict__ gw) {
    int warp = threadIdx.x >> 5;
    int lane = threadIdx.x & 31;
    int token = blockIdx.x * 8 + warp;

    const float* xr = x + (size_t)token * DIM;
    float xv[32];
#pragma unroll
    for (int j = 0; j < 32; j++) xv[j] = xr[j * 32 + lane];

    float logits[NE];
#pragma unroll
    for (int e = 0; e < NE; e++) {
        const float* g = gw + e * DIM;
        float s = 0.0f;
#pragma unroll
        for (int j = 0; j < 32; j++) s += xv[j] * g[j * 32 + lane];
#pragma unroll
        for (int o = 16; o; o >>= 1) s += __shfl_xor_sync(0xffffffffu, s, o);
        logits[e] = s;
    }

    if (lane == 0) {
        int i1 = 0;
#pragma unroll
        for (int e = 1; e < NE; e++)
            if (logits[e] > logits[i1]) i1 = e;
        int i2 = -1;
#pragma unroll
        for (int e = 0; e < NE; e++) {
            if (e == i1) continue;
            if (i2 < 0 || logits[e] > logits[i2]) i2 = e;
        }
        float p1 = 1.0f / (1.0f + __expf(logits[i2] - logits[i1]));
        float p2 = 1.0f - p1;
        int s1 = atomicAdd(&g_counts[i1], 1);
        g_tok[i1 * NTOK + s1] = token;
        g_cw[i1 * NTOK + s1]  = p1;
        int s2 = atomicAdd(&g_counts[i2], 1);
        g_tok[i2 * NTOK + s2] = token;
        g_cw[i2 * NTOK + s2]  = p2;
    }
}

// ---------------- kernel 2: prefix over 8 counts ----------------
__global__ void prefix_kernel() {
    if (threadIdx.x == 0) {
        int a = 0;
        for (int e = 0; e < NE; e++) { g_offsets[e] = a; a += g_counts[e]; }
        g_offsets[NE] = a;
    }
}

// ---------------- tile scheduler ----------------
__device__ __forceinline__ bool find_tile(int bx, int& e, int& tile, int& cnt) {
    int acc = 0;
    e = -1;
#pragma unroll
    for (int ee = 0; ee < NE; ee++) {
        int c = g_counts[ee];
        int t = (c + 127) >> 7;
        if (e < 0 && bx < acc + t) { e = ee; tile = bx - acc; cnt = c; }
        acc += t;
    }
    return e >= 0;
}

// dynamic SMEM: [0:512) stok, [512:1024) scw, stages at 1024 + s*32768
#define STG_BASE 1024
#define STG_SZ   32768
#define SMEM_BYTES (STG_BASE + 3 * STG_SZ)

// ---------------- kernel 3: GEMM1 (x@w1^T, x@w3^T) -> silu*mul -> H(fp16) ----------------
// 128 threads (4 warps, 2Mx2N), BM=128, BN=64 dual, BK=64 halfs, warp tile 64x32 per matrix
__global__ __launch_bounds__(128, 2) void gemm1_kernel() {
    extern __shared__ char dsm[];
    int e, tile, cnt;
    if (!find_tile(blockIdx.x, e, tile, cnt)) return;
    int offs = g_offsets[e];
    int n0 = blockIdx.y * 64;

    int tid = threadIdx.x;
    int* stok = (int*)dsm;
    {
        int i = tile * 128 + tid;
        stok[tid] = (i < cnt) ? g_tok[e * NTOK + i] : -1;
    }
    __syncthreads();

    int warp = tid >> 5, lane = tid & 31;
    int wm = warp >> 1, wn = warp & 1;
    uint32_t sb = smem_u32(dsm);

    // ---- cp.async assignments: A 128x8 chunks (8/thr), B1/B3 64x8 (4/thr each) ----
    const __half* asrc[8]; uint32_t asz[8], adst[8];
#pragma unroll
    for (int j = 0; j < 8; j++) {
        int idx = tid + j * 128;
        int r = idx >> 3, c = idx & 7;
        int t = stok[r];
        asrc[j] = g_xh + (size_t)(t < 0 ? 0 : t) * DIM + c * 8;
        asz[j]  = (t < 0) ? 0u : 16u;
        adst[j] = swb32(r, c);
    }
    const __half* b1src[4]; const __half* b3src[4]; uint32_t bdst[4];
#pragma unroll
    for (int j = 0; j < 4; j++) {
        int idx = tid + j * 128;
        int r = idx >> 3, c = idx & 7;
        b1src[j] = g_w1h + (size_t)e * FF * DIM + (size_t)(n0 + r) * DIM + c * 8;
        b3src[j] = g_w3h + (size_t)e * FF * DIM + (size_t)(n0 + r) * DIM + c * 8;
        bdst[j]  = swb32(r, c);
    }
    auto issue_stage = [&](int s, int kt) {
        uint32_t base = sb + STG_BASE + s * STG_SZ;
        int k0 = kt * 64;
#pragma unroll
        for (int j = 0; j < 8; j++) cpa16(base + adst[j], asrc[j] + k0, asz[j]);
#pragma unroll
        for (int j = 0; j < 4; j++) cpa16(base + 16384 + bdst[j], b1src[j] + k0, 16);
#pragma unroll
        for (int j = 0; j < 4; j++) cpa16(base + 24576 + bdst[j], b3src[j] + k0, 16);
    };

    // ---- ldmatrix fragment offsets ----
    int arow = (((lane >> 3) & 1) << 3) + (lane & 7);
    int acol = lane >> 4;
    int brow = (((lane >> 4) & 1) << 3) + (lane & 7);
    int bcol = (lane >> 3) & 1;
    uint32_t offA[4][4], offB[2][4];
#pragma unroll
    for (int mt = 0; mt < 4; mt++)
#pragma unroll
        for (int kki = 0; kki < 4; kki++)
            offA[mt][kki] = swb32(wm * 64 + mt * 16 + arow, kki * 2 + acol);
#pragma unroll
    for (int p = 0; p < 2; p++)
#pragma unroll
        for (int kki = 0; kki < 4; kki++)
            offB[p][kki] = swb32(wn * 32 + p * 16 + brow, kki * 2 + bcol);

    float acc1[4][4][4] = {};
    float acc3[4][4][4] = {};

    auto compute_stage = [&](int s) {
        uint32_t base = sb + STG_BASE + s * STG_SZ;
        uint32_t aA = base, aB1 = base + 16384, aB3 = base + 24576;
#pragma unroll
        for (int kki = 0; kki < 4; kki++) {
            uint32_t a[4][4];
#pragma unroll
            for (int mt = 0; mt < 4; mt++)
                LDSM4(a[mt][0], a[mt][1], a[mt][2], a[mt][3], aA + offA[mt][kki]);
#pragma unroll
            for (int p = 0; p < 2; p++) {
                uint32_t b1[4], b3[4];
                LDSM4(b1[0], b1[1], b1[2], b1[3], aB1 + offB[p][kki]);
                LDSM4(b3[0], b3[1], b3[2], b3[3], aB3 + offB[p][kki]);
#pragma unroll
                for (int mt = 0; mt < 4; mt++) {
                    mma16(acc1[mt][2 * p],     a[mt], &b1[0]);
                    mma16(acc1[mt][2 * p + 1], a[mt], &b1[2]);
                    mma16(acc3[mt][2 * p],     a[mt], &b3[0]);
                    mma16(acc3[mt][2 * p + 1], a[mt], &b3[2]);
                }
            }
        }
    };

    issue_stage(0, 0); CP_COMMIT();
    issue_stage(1, 1); CP_COMMIT();
#pragma unroll 1
    for (int kt = 0; kt < NKT1; kt++) {
        CP_WAIT1();
        __syncthreads();
        compute_stage(kt % 3);
        if (kt + 2 < NKT1) issue_stage((kt + 2) % 3, kt + 2);
        CP_COMMIT();
    }

    // epilogue: h = silu(s1) * s3 -> g_H (fp16, half2 stores)
#pragma unroll
    for (int mt = 0; mt < 4; mt++) {
#pragma unroll
        for (int nt = 0; nt < 4; nt++) {
            int r0 = wm * 64 + mt * 16 + (lane >> 2);
            int cc = wn * 32 + nt * 8 + ((lane & 3) << 1);
#pragma unroll
            for (int h8 = 0; h8 < 2; h8++) {
                int i = tile * 128 + r0 + h8 * 8;
                if (i < cnt) {
                    float s1a = acc1[mt][nt][2 * h8],     s3a = acc3[mt][nt][2 * h8];
                    float s1b = acc1[mt][nt][2 * h8 + 1], s3b = acc3[mt][nt][2 * h8 + 1];
                    float ha = (s1a / (1.0f + __expf(-s1a))) * s3a;
                    float hb = (s1b / (1.0f + __expf(-s1b))) * s3b;
                    *(__half2*)(g_H + (size_t)(offs + i) * FF + n0 + cc) =
                        __floats2half2_rn(ha, hb);
                }
            }
        }
    }
}

// ---------------- kernel 4: GEMM2 (H @ w2^T), BN=128, scaled scatter-add ----------------
// 128 threads (4 warps, 2Mx2N), BM=128, BN=128, BK=64 halfs, warp tile 64x64
__global__ __launch_bounds__(128, 2) void gemm2_kernel(float* __restrict__ out) {
    extern __shared__ char dsm[];
    int e, tile, cnt;
    if (!find_tile(blockIdx.x, e, tile, cnt)) return;
    int offs = g_offsets[e];
    int n0 = blockIdx.y * 128;

    int tid = threadIdx.x;
    int*   stok = (int*)dsm;
    float* scw  = (float*)(dsm + 512);
    {
        int i = tile * 128 + tid;
        stok[tid] = (i < cnt) ? g_tok[e * NTOK + i] : -1;
        scw[tid]  = (i < cnt) ? g_cw[e * NTOK + i] : 0.0f;
    }
    __syncthreads();

    int warp = tid >> 5, lane = tid & 31;
    int wm = warp >> 1, wn = warp & 1;
    uint32_t sb = smem_u32(dsm);

    // A: 128x8 chunks (8/thr) from g_H; B: 128x8 chunks (8/thr) from w2h
    const __half* asrc[8]; uint32_t asz[8], adst[8];
    const __half* bsrc[8];
#pragma unroll
    for (int j = 0; j < 8; j++) {
        int idx = tid + j * 128;
        int r = idx >> 3, c = idx & 7;
        bool av = (tile * 128 + r) < cnt;
        asrc[j] = g_H + (size_t)(offs + tile * 128 + (av ? r : 0)) * FF + c * 8;
        asz[j]  = av ? 16u : 0u;
        adst[j] = swb32(r, c);
        bsrc[j] = g_w2h + (size_t)e * DIM * FF + (size_t)(n0 + r) * FF + c * 8;
    }
    auto issue_stage = [&](int s, int kt) {
        uint32_t base = sb + STG_BASE + s * STG_SZ;
        int k0 = kt * 64;
#pragma unroll
        for (int j = 0; j < 8; j++) cpa16(base + adst[j], asrc[j] + k0, asz[j]);
#pragma unroll
        for (int j = 0; j < 8; j++) cpa16(base + 16384 + adst[j], bsrc[j] + k0, 16);
    };

    int arow = (((lane >> 3) & 1) << 3) + (lane & 7);
    int acol = lane >> 4;
    int brow = (((lane >> 4) & 1) << 3) + (lane & 7);
    int bcol = (lane >> 3) & 1;
    uint32_t offA[4][4], offB[4][4];
#pragma unroll
    for (int mt = 0; mt < 4; mt++)
#pragma unroll
        for (int kki = 0; kki < 4; kki++)
            offA[mt][kki] = swb32(wm * 64 + mt * 16 + arow, kki * 2 + acol);
#pragma unroll
    for (int p = 0; p < 4; p++)
#pragma unroll
        for (int kki = 0; kki < 4; kki++)
            offB[p][kki] = swb32(wn * 64 + p * 16 + brow, kki * 2 + bcol);

    float acc[4][8][4] = {};

    auto compute_stage = [&](int s) {
        uint32_t base = sb + STG_BASE + s * STG_SZ;
        uint32_t aA = base, aB = base + 16384;
#pragma unroll
        for (int kki = 0; kki < 4; kki++) {
            uint32_t a[4][4];
#pragma unroll
            for (int mt = 0; mt < 4; mt++)
                LDSM4(a[mt][0], a[mt][1], a[mt][2], a[mt][3], aA + offA[mt][kki]);
#pragma unroll
            for (int p = 0; p < 4; p++) {
                uint32_t b[4];
                LDSM4(b[0], b[1], b[2], b[3], aB + offB[p][kki]);
#pragma unroll
                for (int mt = 0; mt < 4; mt++) {
                    mma16(acc[mt][2 * p],     a[mt], &b[0]);
                    mma16(acc[mt][2 * p + 1], a[mt], &b[2]);
                }
            }
        }
    };

    issue_stage(0, 0); CP_COMMIT();
    issue_stage(1, 1); CP_COMMIT();
#pragma unroll 1
    for (int kt = 0; kt < NKT2; kt++) {
        CP_WAIT1();
        __syncthreads();
        compute_stage(kt % 3);
        if (kt + 2 < NKT2) issue_stage((kt + 2) % 3, kt + 2);
        CP_COMMIT();
    }

    // epilogue: out[token, n] += cw * acc  (2 commutative adds/elem -> deterministic)
#pragma unroll
    for (int mt = 0; mt < 4; mt++) {
#pragma unroll
        for (int nt = 0; nt < 8; nt++) {
#pragma unroll
            for (int q = 0; q < 4; q++) {
                int r  = wm * 64 + mt * 16 + (lane >> 2) + ((q >= 2) ? 8 : 0);
                int cc = wn * 64 + nt * 8 + ((lane & 3) << 1) + (q & 1);
                int i = tile * 128 + r;
                if (i < cnt) {
                    int t  = stok[r];
                    float w = scw[r];
                    atomicAdd(&out[(size_t)t * DIM + n0 + cc], acc[mt][nt][q] * w);
                }
            }
        }
    }
}

// ---------------- launch ----------------
extern "C" void kernel_launch(void* const* d_in, const int* in_sizes, int n_in,
                              void* d_out, int out_size) {
    const float* x  = (const float*)d_in[0];
    const float* gw = (const float*)d_in[1];
    const float* w1 = (const float*)d_in[2];
    const float* w2 = (const float*)d_in[3];
    const float* w3 = (const float*)d_in[4];
    float* out = (float*)d_out;

    cudaFuncSetAttribute(gemm1_kernel, cudaFuncAttributeMaxDynamicSharedMemorySize, SMEM_BYTES);
    cudaFuncSetAttribute(gemm2_kernel, cudaFuncAttributeMaxDynamicSharedMemorySize, SMEM_BYTES);

    __half *xh, *w1h, *w2h, *w3h;
    cudaGetSymbolAddress((void**)&xh,  g_xh);
    cudaGetSymbolAddress((void**)&w1h, g_w1h);
    cudaGetSymbolAddress((void**)&w2h, g_w2h);
    cudaGetSymbolAddress((void**)&w3h, g_w3h);

    int nx4 = NTOK * DIM / 4;
    int nw4 = NE * FF * DIM / 4;
    tohalf_kernel<<<(nx4 + 255) / 256, 256>>>(x, xh, nx4);
    tohalf_kernel<<<(nw4 + 255) / 256, 256>>>(w1, w1h, nw4);
    tohalf_kernel<<<(nw4 + 255) / 256, 256>>>(w2, w2h, nw4);
    tohalf_kernel<<<(nw4 + 255) / 256, 256>>>(w3, w3h, nw4);

    zero_kernel<<<(out_size + 255) / 256, 256>>>(out, out_size);
    gate_kernel<<<NTOK / 8, 256>>>(x, gw);
    prefix_kernel<<<1, 32>>>();
    gemm1_kernel<<<dim3(264, FF / 64), 128, SMEM_BYTES>>>();
    gemm2_kernel<<<dim3(264, DIM / 128), 128, SMEM_BYTES>>>(out);
}